// round 14
// baseline (speedup 1.0000x reference)
#include <cuda_runtime.h>
#include <cuda_fp16.h>
#include <math.h>
#include <stdint.h>

#define T_TOK   2048
#define HDIM    2048
#define NEXP    8
#define IDIM    5632
#define TWOI    11264
#define NASSIGN 4096
#define MAXT    40
#define PADROWS (NASSIGN + 256)

#define BM 128
#define BN 128
#define BK 32
#define PITCH 40                 // fp16 elems per tile row (80B)
#define FPITCHB 144              // fp32 staging pitch (bytes)

// smem layout (bytes)
#define AT0 0
#define AT1 10240
#define BT  20480
#define FB0 30720
#define FB1 49152
#define SMEM_BYTES 67584

// ---------------- routing / scheduling state ----------------
__device__ int   g_perm_token[NASSIGN];
__device__ float g_perm_gate[NASSIGN];
__device__ int   g_se[MAXT], g_sm0[MAXT], g_srows[MAXT];

// ---------------- fp16 operands / scratch ----------------
__device__ __align__(128) __half g_af[(size_t)PADROWS * HDIM];   // gathered X fp16
__device__ __align__(128) __half g_h [(size_t)PADROWS * IDIM];   // activation fp16

// ================= helpers =================
__device__ __forceinline__ uint32_t smem_to_u32(const void* p) {
    uint32_t a;
    asm("{ .reg .u64 t; cvta.to.shared.u64 t, %1; cvt.u32.u64 %0, t; }" : "=r"(a) : "l"(p));
    return a;
}
__device__ __forceinline__ void cp16(uint32_t dst, const void* src) {
    asm volatile("cp.async.cg.shared.global [%0], [%1], 16;" :: "r"(dst), "l"(src));
}
__device__ __forceinline__ void ldsm4(uint32_t* r, uint32_t addr) {
    asm volatile("ldmatrix.sync.aligned.m8n8.x4.shared.b16 {%0,%1,%2,%3}, [%4];"
                 : "=r"(r[0]), "=r"(r[1]), "=r"(r[2]), "=r"(r[3]) : "r"(addr));
}
__device__ __forceinline__ void mma16816(float* d, const uint32_t* a, const uint32_t* b) {
    asm volatile(
        "mma.sync.aligned.m16n8k16.row.col.f32.f16.f16.f32 "
        "{%0,%1,%2,%3}, {%4,%5,%6,%7}, {%8,%9}, {%0,%1,%2,%3};"
        : "+f"(d[0]), "+f"(d[1]), "+f"(d[2]), "+f"(d[3])
        : "r"(a[0]), "r"(a[1]), "r"(a[2]), "r"(a[3]), "r"(b[0]), "r"(b[1]));
}
__device__ __forceinline__ void lds128f(float4& v, uint32_t a) {
    asm volatile("ld.shared.v4.f32 {%0,%1,%2,%3}, [%4];"
                 : "=f"(v.x), "=f"(v.y), "=f"(v.z), "=f"(v.w) : "r"(a));
}
__device__ __forceinline__ void sts128(uint32_t a, uint32_t x, uint32_t y, uint32_t z, uint32_t w) {
    asm volatile("st.shared.v4.b32 [%0], {%1,%2,%3,%4};" :: "r"(a), "r"(x), "r"(y), "r"(z), "r"(w));
}
__device__ __forceinline__ uint32_t cvt2(float f0, float f1) {
    __half2 hh = __floats2half2_rn(f0, f1);
    return *(uint32_t*)&hh;
}

// ================= routing =================
__global__ void route_kernel(const float* __restrict__ logits)
{
    __shared__ int s_cnt[NEXP], s_off[NEXP + 1], s_cur[NEXP];
    const int tid = threadIdx.x;
    if (tid < NEXP) s_cnt[tid] = 0;
    __syncthreads();
    for (int t = tid; t < T_TOK; t += blockDim.x) {
        const float* l = logits + t * NEXP;
        int i1 = 0; float v1 = l[0];
        #pragma unroll
        for (int e = 1; e < NEXP; e++) { float v = l[e]; if (v > v1) { v1 = v; i1 = e; } }
        int i2 = -1; float v2 = -3.0e38f;
        #pragma unroll
        for (int e = 0; e < NEXP; e++) { if (e == i1) continue; float v = l[e]; if (v > v2) { v2 = v; i2 = e; } }
        atomicAdd(&s_cnt[i1], 1); atomicAdd(&s_cnt[i2], 1);
    }
    __syncthreads();
    if (tid == 0) {
        int acc = 0;
        for (int e = 0; e < NEXP; e++) { s_off[e] = acc; s_cur[e] = acc; acc += s_cnt[e]; }
        s_off[NEXP] = acc;
    }
    __syncthreads();
    for (int t = tid; t < T_TOK; t += blockDim.x) {
        const float* l = logits + t * NEXP;
        int i1 = 0; float v1 = l[0];
        #pragma unroll
        for (int e = 1; e < NEXP; e++) { float v = l[e]; if (v > v1) { v1 = v; i1 = e; } }
        int i2 = -1; float v2 = -3.0e38f;
        #pragma unroll
        for (int e = 0; e < NEXP; e++) { if (e == i1) continue; float v = l[e]; if (v > v2) { v2 = v; i2 = e; } }
        float g1 = 1.0f / (1.0f + expf(v2 - v1));
        float g2 = 1.0f - g1;
        int s1 = atomicAdd(&s_cur[i1], 1);
        g_perm_token[s1] = t; g_perm_gate[s1] = g1;
        int s2 = atomicAdd(&s_cur[i2], 1);
        g_perm_token[s2] = t; g_perm_gate[s2] = g2;
    }
    __syncthreads();
    if (tid == 0) {
        int nt = 0;
        for (int e = 0; e < NEXP; e++) {
            int off = s_off[e], cnt = s_cnt[e];
            for (int r = 0; r < cnt; r += BM) {
                g_se[nt] = e; g_sm0[nt] = off + r;
                g_srows[nt] = (cnt - r < BM) ? (cnt - r) : BM; nt++;
            }
        }
        for (; nt < MAXT; nt++) g_srows[nt] = 0;
    }
}

__global__ void zero_kernel(float4* __restrict__ out)
{
    int idx = blockIdx.x * blockDim.x + threadIdx.x;
    if (idx < (T_TOK * HDIM) / 4) out[idx] = make_float4(0.f, 0.f, 0.f, 0.f);
}

// gather X rows by perm token -> fp16
__global__ void permA_kernel(const float* __restrict__ X)
{
    int idx = blockIdx.x * blockDim.x + threadIdx.x;
    if (idx >= NASSIGN * HDIM / 4) return;
    int r = idx / (HDIM / 4);
    int c = (idx % (HDIM / 4)) * 4;
    int t = g_perm_token[r];
    float4 x = *(const float4*)(X + (size_t)t * HDIM + c);
    uint2 p; p.x = cvt2(x.x, x.y); p.y = cvt2(x.z, x.w);
    *(uint2*)(g_af + (size_t)r * HDIM + c) = p;
}

// convert fp32 B staging (128 rows x 32) -> fp16 B tile; 16 fp32 per thread
__device__ __forceinline__ void convert_B(uint32_t sb, uint32_t fb_off, int tid)
{
    const int r = tid >> 1, half = tid & 1;
    const uint32_t fb = sb + fb_off + r * FPITCHB + half * 64;
    float4 x0, x1, x2, x3;
    lds128f(x0, fb); lds128f(x1, fb + 16); lds128f(x2, fb + 32); lds128f(x3, fb + 48);
    const uint32_t d = sb + BT + (r * PITCH + half * 16) * 2;
    sts128(d,      cvt2(x0.x, x0.y), cvt2(x0.z, x0.w), cvt2(x1.x, x1.y), cvt2(x1.z, x1.w));
    sts128(d + 16, cvt2(x2.x, x2.y), cvt2(x2.z, x2.w), cvt2(x3.x, x3.y), cvt2(x3.z, x3.w));
}

// ============ 128x128 GEMM, 256 thr, 2 CTA/SM; B fp32 converted in-loop ============
// EPI 1: A = g_af, B = w13 fp32 (g/u paired rows), fused silu -> g_h
// EPI 2: A = g_h,  B = w2 fp32, gated atomicAdd -> out
template<int KD, int EPI, int KSPLIT>
__global__ __launch_bounds__(256, 2) void gemm_fused(
    const float* __restrict__ W, float* __restrict__ outp)
{
    constexpr int NCH = KD / (BK * KSPLIT);

    const int bt    = blockIdx.x;
    const int mrows = g_srows[bt];
    if (mrows == 0) return;
    const int e   = g_se[bt];
    const int m0  = g_sm0[bt];
    const int kk0 = (KSPLIT > 1) ? blockIdx.z * (KD / KSPLIT) : 0;
    const float* Bw = W + (size_t)e * ((EPI == 1) ? (size_t)TWOI * KD : (size_t)HDIM * KD);

    extern __shared__ char smem[];
    const uint32_t sb = smem_to_u32(smem);
    const int tid  = threadIdx.x;
    const int wid  = tid >> 5;
    const int lane = tid & 31;
    const int wm   = (wid & 3) << 5;    // 0..96
    const int wn   = (wid >> 2) << 6;   // 0 or 64

    // ---- A fp16 endpoints: 2 chunks/thread ----
    const __half* Aarr = (EPI == 1) ? g_af : g_h;
    const __half* srcA0 = Aarr + (size_t)(m0 + (tid >> 2)) * KD + kk0 + (tid & 3) * 8;
    const __half* srcA1 = srcA0 + (size_t)64 * KD;
    const uint32_t dA0 = ((tid >> 2) * PITCH + (tid & 3) * 8) * 2;
    const uint32_t dA1 = dA0 + 64 * PITCH * 2;

    // ---- B fp32 endpoints: 4 chunks/thread (rows tid>>3 + {0,32,64,96}) ----
    const float* srcB[4];
    {
        const int rb = tid >> 3, cg = (tid & 7) * 4;
        #pragma unroll
        for (int j = 0; j < 4; j++) {
            const int r = rb + j * 32;
            int grow;
            if (EPI == 1) {
                const int wg = r >> 6, inner = r & 63;
                const int n0g = blockIdx.y * 64;
                grow = (inner < 32) ? (n0g + wg * 32 + inner)
                                    : (IDIM + n0g + wg * 32 + inner - 32);
            } else {
                grow = blockIdx.y * BN + r;
            }
            srcB[j] = Bw + (size_t)grow * KD + kk0 + cg;
        }
    }
    const uint32_t dB = (tid >> 3) * FPITCHB + (tid & 7) * 16;

    const uint32_t a_off = ((wm + (lane & 15)) * PITCH + ((lane >> 4) << 3)) * 2;
    const uint32_t b_off = ((wn + ((lane >> 4) << 3) + (lane & 7)) * PITCH + (((lane >> 3) & 1) << 3)) * 2;

    float acc[2][8][4];
    #pragma unroll
    for (int i = 0; i < 2; i++)
        #pragma unroll
        for (int j = 0; j < 8; j++)
            #pragma unroll
            for (int q = 0; q < 4; q++) acc[i][j][q] = 0.f;

    // prologue: stage 0 into buffers 0
    cp16(sb + AT0 + dA0, srcA0); cp16(sb + AT0 + dA1, srcA1);
    #pragma unroll
    for (int j = 0; j < 4; j++) cp16(sb + FB0 + dB + j * 32 * FPITCHB, srcB[j]);
    asm volatile("cp.async.commit_group;" ::: "memory");
    srcA0 += BK; srcA1 += BK;
    #pragma unroll
    for (int j = 0; j < 4; j++) srcB[j] += BK;

    for (int i = 0; i < NCH; i++) {
        const int b = i & 1;
        asm volatile("cp.async.wait_group 0;" ::: "memory");
        __syncthreads();              // stage i visible; all warps done with mma(i-1)

        if (i + 1 < NCH) {            // prefetch i+1 into buffers 1-b
            const uint32_t at = sb + ((1 - b) ? AT1 : AT0);
            cp16(at + dA0, srcA0); cp16(at + dA1, srcA1);
            const uint32_t fb = sb + ((1 - b) ? FB1 : FB0);
            #pragma unroll
            for (int j = 0; j < 4; j++) cp16(fb + dB + j * 32 * FPITCHB, srcB[j]);
            srcA0 += BK; srcA1 += BK;
            #pragma unroll
            for (int j = 0; j < 4; j++) srcB[j] += BK;
        }
        asm volatile("cp.async.commit_group;" ::: "memory");

        convert_B(sb, b ? FB1 : FB0, tid);
        __syncthreads();              // BT ready

        const uint32_t at = sb + (b ? AT1 : AT0);
        #pragma unroll
        for (int ks = 0; ks < BK; ks += 16) {
            uint32_t afr[2][4], bfr[4][4];
            ldsm4(afr[0], at + a_off + ks * 2);
            ldsm4(afr[1], at + a_off + (16 * PITCH + ks) * 2);
            #pragma unroll
            for (int jn = 0; jn < 4; jn++)
                ldsm4(bfr[jn], sb + BT + b_off + (jn * 16 * PITCH + ks) * 2);
            #pragma unroll
            for (int im = 0; im < 2; im++)
                #pragma unroll
                for (int jn = 0; jn < 4; jn++) {
                    mma16816(acc[im][2 * jn],     afr[im], &bfr[jn][0]);
                    mma16816(acc[im][2 * jn + 1], afr[im], &bfr[jn][2]);
                }
        }
    }

    // ---------------- epilogue ----------------
    if (EPI == 1) {
        const int n0g  = blockIdx.y * 64;
        const int wg32 = (wn >> 6) * 32;
        #pragma unroll
        for (int im = 0; im < 2; im++) {
            #pragma unroll
            for (int half = 0; half < 2; half++) {
                const int rloc = wm + im * 16 + half * 8 + (lane >> 2);
                if (rloc >= mrows) continue;
                __half* hrow = g_h + (size_t)(m0 + rloc) * IDIM + n0g + wg32;
                #pragma unroll
                for (int jn8 = 0; jn8 < 4; jn8++) {
                    const float gv0 = acc[im][jn8][half * 2 + 0];
                    const float gv1 = acc[im][jn8][half * 2 + 1];
                    const float uv0 = acc[im][jn8 + 4][half * 2 + 0];
                    const float uv1 = acc[im][jn8 + 4][half * 2 + 1];
                    const float h0 = gv0 / (1.0f + expf(-gv0)) * uv0;
                    const float h1 = gv1 / (1.0f + expf(-gv1)) * uv1;
                    const int col = jn8 * 8 + ((lane & 3) << 1);
                    *(uint32_t*)(hrow + col) = cvt2(h0, h1);
                }
            }
        }
    } else {
        const int n0 = blockIdx.y * BN;
        #pragma unroll
        for (int im = 0; im < 2; im++) {
            #pragma unroll
            for (int half = 0; half < 2; half++) {
                const int rloc = wm + im * 16 + half * 8 + (lane >> 2);
                if (rloc >= mrows) continue;
                const int   tok  = g_perm_token[m0 + rloc];
                const float gate = g_perm_gate[m0 + rloc];
                #pragma unroll
                for (int jn8 = 0; jn8 < 8; jn8++) {
                    const int col = n0 + wn + jn8 * 8 + ((lane & 3) << 1);
                    float* dst = outp + (size_t)tok * HDIM + col;
                    atomicAdd(dst + 0, gate * acc[im][jn8][half * 2 + 0]);
                    atomicAdd(dst + 1, gate * acc[im][jn8][half * 2 + 1]);
                }
            }
        }
    }
}

// ================= launch =================
extern "C" void kernel_launch(void* const* d_in, const int* in_sizes, int n_in,
                              void* d_out, int out_size)
{
    const float* hs     = (const float*)d_in[0];
    const float* logits = (const float*)d_in[1];
    const float* w13    = (const float*)d_in[2];
    const float* w2     = (const float*)d_in[3];
    float* out = (float*)d_out;

    cudaFuncSetAttribute(gemm_fused<HDIM, 1, 1>, cudaFuncAttributeMaxDynamicSharedMemorySize, SMEM_BYTES);
    cudaFuncSetAttribute(gemm_fused<IDIM, 2, 2>, cudaFuncAttributeMaxDynamicSharedMemorySize, SMEM_BYTES);

    zero_kernel<<<(T_TOK * HDIM / 4 + 255) / 256, 256>>>((float4*)out);
    route_kernel<<<1, 256>>>(logits);
    permA_kernel<<<(NASSIGN * HDIM / 4 + 255) / 256, 256>>>(hs);

    // GEMM1: grid (M-tiles, IDIM/64 h-col blocks)
    gemm_fused<HDIM, 1, 1><<<dim3(MAXT, IDIM / 64, 1), 256, SMEM_BYTES>>>(w13, nullptr);
    // GEMM2: grid (M-tiles, HDIM/128, split-K 2)
    gemm_fused<IDIM, 2, 2><<<dim3(MAXT, HDIM / BN, 2), 256, SMEM_BYTES>>>(w2, out);
}

// round 15
// speedup vs baseline: 1.0769x; 1.0769x over previous
#include <cuda_runtime.h>
#include <cuda_fp16.h>
#include <math.h>
#include <stdint.h>

#define T_TOK   2048
#define HDIM    2048
#define NEXP    8
#define IDIM    5632
#define TWOI    11264
#define NASSIGN 4096
#define MAXT    40
#define PADROWS (NASSIGN + 256)

#define BM 128
#define BN 128
#define BK 32
#define PITCH 40                 // fp16 elems per tile row (80B)
#define FPITCHB 144              // fp32 staging pitch (bytes)

// smem layout (bytes): A fp16 x3, B fp16 tile x2, B fp32 staging x3
#define ATSZ 10240
#define FBSZ 18432
#define AT_OFF(k) ((k) * ATSZ)                    // 0, 10240, 20480
#define BT_OFF(k) (30720 + (k) * ATSZ)            // 30720, 40960
#define FB_OFF(k) (51200 + (k) * FBSZ)            // 51200, 69632, 88064
#define SMEM_BYTES 106496

// ---------------- routing / scheduling state ----------------
__device__ int   g_perm_token[NASSIGN];
__device__ float g_perm_gate[NASSIGN];
__device__ int   g_se[MAXT], g_sm0[MAXT], g_srows[MAXT];

// ---------------- fp16 operands / scratch ----------------
__device__ __align__(128) __half g_af[(size_t)PADROWS * HDIM];   // gathered X fp16
__device__ __align__(128) __half g_h [(size_t)PADROWS * IDIM];   // activation fp16

// ================= helpers =================
__device__ __forceinline__ uint32_t smem_to_u32(const void* p) {
    uint32_t a;
    asm("{ .reg .u64 t; cvta.to.shared.u64 t, %1; cvt.u32.u64 %0, t; }" : "=r"(a) : "l"(p));
    return a;
}
__device__ __forceinline__ void cp16(uint32_t dst, const void* src) {
    asm volatile("cp.async.cg.shared.global [%0], [%1], 16;" :: "r"(dst), "l"(src));
}
__device__ __forceinline__ void ldsm4(uint32_t* r, uint32_t addr) {
    asm volatile("ldmatrix.sync.aligned.m8n8.x4.shared.b16 {%0,%1,%2,%3}, [%4];"
                 : "=r"(r[0]), "=r"(r[1]), "=r"(r[2]), "=r"(r[3]) : "r"(addr));
}
__device__ __forceinline__ void mma16816(float* d, const uint32_t* a, const uint32_t* b) {
    asm volatile(
        "mma.sync.aligned.m16n8k16.row.col.f32.f16.f16.f32 "
        "{%0,%1,%2,%3}, {%4,%5,%6,%7}, {%8,%9}, {%0,%1,%2,%3};"
        : "+f"(d[0]), "+f"(d[1]), "+f"(d[2]), "+f"(d[3])
        : "r"(a[0]), "r"(a[1]), "r"(a[2]), "r"(a[3]), "r"(b[0]), "r"(b[1]));
}
__device__ __forceinline__ void lds128f(float4& v, uint32_t a) {
    asm volatile("ld.shared.v4.f32 {%0,%1,%2,%3}, [%4];"
                 : "=f"(v.x), "=f"(v.y), "=f"(v.z), "=f"(v.w) : "r"(a));
}
__device__ __forceinline__ void sts128(uint32_t a, uint32_t x, uint32_t y, uint32_t z, uint32_t w) {
    asm volatile("st.shared.v4.b32 [%0], {%1,%2,%3,%4};" :: "r"(a), "r"(x), "r"(y), "r"(z), "r"(w));
}
__device__ __forceinline__ uint32_t cvt2(float f0, float f1) {
    __half2 hh = __floats2half2_rn(f0, f1);
    return *(uint32_t*)&hh;
}

// ================= routing =================
__global__ void route_kernel(const float* __restrict__ logits)
{
    __shared__ int s_cnt[NEXP], s_off[NEXP + 1], s_cur[NEXP];
    const int tid = threadIdx.x;
    if (tid < NEXP) s_cnt[tid] = 0;
    __syncthreads();
    for (int t = tid; t < T_TOK; t += blockDim.x) {
        const float* l = logits + t * NEXP;
        int i1 = 0; float v1 = l[0];
        #pragma unroll
        for (int e = 1; e < NEXP; e++) { float v = l[e]; if (v > v1) { v1 = v; i1 = e; } }
        int i2 = -1; float v2 = -3.0e38f;
        #pragma unroll
        for (int e = 0; e < NEXP; e++) { if (e == i1) continue; float v = l[e]; if (v > v2) { v2 = v; i2 = e; } }
        atomicAdd(&s_cnt[i1], 1); atomicAdd(&s_cnt[i2], 1);
    }
    __syncthreads();
    if (tid == 0) {
        int acc = 0;
        for (int e = 0; e < NEXP; e++) { s_off[e] = acc; s_cur[e] = acc; acc += s_cnt[e]; }
        s_off[NEXP] = acc;
    }
    __syncthreads();
    for (int t = tid; t < T_TOK; t += blockDim.x) {
        const float* l = logits + t * NEXP;
        int i1 = 0; float v1 = l[0];
        #pragma unroll
        for (int e = 1; e < NEXP; e++) { float v = l[e]; if (v > v1) { v1 = v; i1 = e; } }
        int i2 = -1; float v2 = -3.0e38f;
        #pragma unroll
        for (int e = 0; e < NEXP; e++) { if (e == i1) continue; float v = l[e]; if (v > v2) { v2 = v; i2 = e; } }
        float g1 = 1.0f / (1.0f + expf(v2 - v1));
        float g2 = 1.0f - g1;
        int s1 = atomicAdd(&s_cur[i1], 1);
        g_perm_token[s1] = t; g_perm_gate[s1] = g1;
        int s2 = atomicAdd(&s_cur[i2], 1);
        g_perm_token[s2] = t; g_perm_gate[s2] = g2;
    }
    __syncthreads();
    if (tid == 0) {
        int nt = 0;
        for (int e = 0; e < NEXP; e++) {
            int off = s_off[e], cnt = s_cnt[e];
            for (int r = 0; r < cnt; r += BM) {
                g_se[nt] = e; g_sm0[nt] = off + r;
                g_srows[nt] = (cnt - r < BM) ? (cnt - r) : BM; nt++;
            }
        }
        for (; nt < MAXT; nt++) g_srows[nt] = 0;
    }
}

__global__ void zero_kernel(float4* __restrict__ out)
{
    int idx = blockIdx.x * blockDim.x + threadIdx.x;
    if (idx < (T_TOK * HDIM) / 4) out[idx] = make_float4(0.f, 0.f, 0.f, 0.f);
}

// gather X rows by perm token -> fp16
__global__ void permA_kernel(const float* __restrict__ X)
{
    int idx = blockIdx.x * blockDim.x + threadIdx.x;
    if (idx >= NASSIGN * HDIM / 4) return;
    int r = idx / (HDIM / 4);
    int c = (idx % (HDIM / 4)) * 4;
    int t = g_perm_token[r];
    float4 x = *(const float4*)(X + (size_t)t * HDIM + c);
    uint2 p; p.x = cvt2(x.x, x.y); p.y = cvt2(x.z, x.w);
    *(uint2*)(g_af + (size_t)r * HDIM + c) = p;
}

// convert fp32 B staging (128 rows x 32) -> fp16 B tile; 16 fp32 per thread
__device__ __forceinline__ void convert_B(uint32_t sb, uint32_t fb_off, uint32_t bt_off, int tid)
{
    const int r = tid >> 1, half = tid & 1;
    const uint32_t fb = sb + fb_off + r * FPITCHB + half * 64;
    float4 x0, x1, x2, x3;
    lds128f(x0, fb); lds128f(x1, fb + 16); lds128f(x2, fb + 32); lds128f(x3, fb + 48);
    const uint32_t d = sb + bt_off + (r * PITCH + half * 16) * 2;
    sts128(d,      cvt2(x0.x, x0.y), cvt2(x0.z, x0.w), cvt2(x1.x, x1.y), cvt2(x1.z, x1.w));
    sts128(d + 16, cvt2(x2.x, x2.y), cvt2(x2.z, x2.w), cvt2(x3.x, x3.y), cvt2(x3.z, x3.w));
}

// ============ 128x128 GEMM, 256 thr, 2 CTA/SM; B fp32, pipelined in-loop cvt ============
// EPI 1: A = g_af, B = w13 fp32 (g/u paired rows), fused silu -> g_h
// EPI 2: A = g_h,  B = w2 fp32, gated atomicAdd -> out
template<int KD, int EPI, int KSPLIT>
__global__ __launch_bounds__(256, 2) void gemm_fused(
    const float* __restrict__ W, float* __restrict__ outp)
{
    constexpr int NCH = KD / (BK * KSPLIT);

    const int bt    = blockIdx.x;
    const int mrows = g_srows[bt];
    if (mrows == 0) return;
    const int e   = g_se[bt];
    const int m0  = g_sm0[bt];
    const int kk0 = (KSPLIT > 1) ? blockIdx.z * (KD / KSPLIT) : 0;
    const float* Bw = W + (size_t)e * ((EPI == 1) ? (size_t)TWOI * KD : (size_t)HDIM * KD);

    extern __shared__ char smem[];
    const uint32_t sb = smem_to_u32(smem);
    const int tid  = threadIdx.x;
    const int wid  = tid >> 5;
    const int lane = tid & 31;
    const int wm   = (wid & 3) << 5;    // 0..96
    const int wn   = (wid >> 2) << 6;   // 0 or 64

    // ---- A fp16 endpoints: 2 chunks/thread ----
    const __half* Aarr = (EPI == 1) ? g_af : g_h;
    const __half* srcA0 = Aarr + (size_t)(m0 + (tid >> 2)) * KD + kk0 + (tid & 3) * 8;
    const __half* srcA1 = srcA0 + (size_t)64 * KD;
    const uint32_t dA0 = ((tid >> 2) * PITCH + (tid & 3) * 8) * 2;
    const uint32_t dA1 = dA0 + 64 * PITCH * 2;

    // ---- B fp32 endpoints: 4 chunks/thread (rows tid>>3 + {0,32,64,96}) ----
    const float* srcB[4];
    {
        const int rb = tid >> 3, cg = (tid & 7) * 4;
        #pragma unroll
        for (int j = 0; j < 4; j++) {
            const int r = rb + j * 32;
            int grow;
            if (EPI == 1) {
                const int wg = r >> 6, inner = r & 63;
                const int n0g = blockIdx.y * 64;
                grow = (inner < 32) ? (n0g + wg * 32 + inner)
                                    : (IDIM + n0g + wg * 32 + inner - 32);
            } else {
                grow = blockIdx.y * BN + r;
            }
            srcB[j] = Bw + (size_t)grow * KD + kk0 + cg;
        }
    }
    const uint32_t dB = (tid >> 3) * FPITCHB + (tid & 7) * 16;

    const uint32_t a_off = ((wm + (lane & 15)) * PITCH + ((lane >> 4) << 3)) * 2;
    const uint32_t b_off = ((wn + ((lane >> 4) << 3) + (lane & 7)) * PITCH + (((lane >> 3) & 1) << 3)) * 2;

    float acc[2][8][4];
    #pragma unroll
    for (int i = 0; i < 2; i++)
        #pragma unroll
        for (int j = 0; j < 8; j++)
            #pragma unroll
            for (int q = 0; q < 4; q++) acc[i][j][q] = 0.f;

    // ---- prologue: stages 0 and 1 in flight ----
    cp16(sb + AT_OFF(0) + dA0, srcA0); cp16(sb + AT_OFF(0) + dA1, srcA1);
    #pragma unroll
    for (int j = 0; j < 4; j++) cp16(sb + FB_OFF(0) + dB + j * 32 * FPITCHB, srcB[j]);
    asm volatile("cp.async.commit_group;" ::: "memory");
    srcA0 += BK; srcA1 += BK;
    #pragma unroll
    for (int j = 0; j < 4; j++) srcB[j] += BK;

    if (NCH > 1) {
        cp16(sb + AT_OFF(1) + dA0, srcA0); cp16(sb + AT_OFF(1) + dA1, srcA1);
        #pragma unroll
        for (int j = 0; j < 4; j++) cp16(sb + FB_OFF(1) + dB + j * 32 * FPITCHB, srcB[j]);
        srcA0 += BK; srcA1 += BK;
        #pragma unroll
        for (int j = 0; j < 4; j++) srcB[j] += BK;
    }
    asm volatile("cp.async.commit_group;" ::: "memory");

    // stage 0 staging arrived -> convert to BT0
    asm volatile("cp.async.wait_group 1;" ::: "memory");
    __syncthreads();
    convert_B(sb, FB_OFF(0), BT_OFF(0), tid);

    int a2 = 2 % 3;   // rotating indices: stage i -> AT/FB[i%3], BT[i%2]
    for (int i = 0; i < NCH; i++) {
        // stage i+1 staging must be fully arrived (converted below)
        asm volatile("cp.async.wait_group 0;" ::: "memory");
        __syncthreads();   // stage i+1 visible; all warps done with stage i-1 buffers

        // issue stage i+2 loads into buffers freed at this barrier
        if (i + 2 < NCH) {
            cp16(sb + AT_OFF(a2) + dA0, srcA0); cp16(sb + AT_OFF(a2) + dA1, srcA1);
            #pragma unroll
            for (int j = 0; j < 4; j++) cp16(sb + FB_OFF(a2) + dB + j * 32 * FPITCHB, srcB[j]);
            srcA0 += BK; srcA1 += BK;
            #pragma unroll
            for (int j = 0; j < 4; j++) srcB[j] += BK;
        }
        asm volatile("cp.async.commit_group;" ::: "memory");
        a2++; if (a2 == 3) a2 = 0;

        // convert stage i+1 (parallel with mma(i) below — no barrier between)
        if (i + 1 < NCH)
            convert_B(sb, FB_OFF((i + 1) % 3), BT_OFF((i + 1) & 1), tid);

        // mma on stage i
        const uint32_t at = sb + AT_OFF(i % 3);
        const uint32_t btt = sb + BT_OFF(i & 1);
        #pragma unroll
        for (int ks = 0; ks < BK; ks += 16) {
            uint32_t afr[2][4], bfr[4][4];
            ldsm4(afr[0], at + a_off + ks * 2);
            ldsm4(afr[1], at + a_off + (16 * PITCH + ks) * 2);
            #pragma unroll
            for (int jn = 0; jn < 4; jn++)
                ldsm4(bfr[jn], btt + b_off + (jn * 16 * PITCH + ks) * 2);
            #pragma unroll
            for (int im = 0; im < 2; im++)
                #pragma unroll
                for (int jn = 0; jn < 4; jn++) {
                    mma16816(acc[im][2 * jn],     afr[im], &bfr[jn][0]);
                    mma16816(acc[im][2 * jn + 1], afr[im], &bfr[jn][2]);
                }
        }
    }

    // ---------------- epilogue ----------------
    if (EPI == 1) {
        const int n0g  = blockIdx.y * 64;
        const int wg32 = (wn >> 6) * 32;
        #pragma unroll
        for (int im = 0; im < 2; im++) {
            #pragma unroll
            for (int half = 0; half < 2; half++) {
                const int rloc = wm + im * 16 + half * 8 + (lane >> 2);
                if (rloc >= mrows) continue;
                __half* hrow = g_h + (size_t)(m0 + rloc) * IDIM + n0g + wg32;
                #pragma unroll
                for (int jn8 = 0; jn8 < 4; jn8++) {
                    const float gv0 = acc[im][jn8][half * 2 + 0];
                    const float gv1 = acc[im][jn8][half * 2 + 1];
                    const float uv0 = acc[im][jn8 + 4][half * 2 + 0];
                    const float uv1 = acc[im][jn8 + 4][half * 2 + 1];
                    const float h0 = gv0 / (1.0f + expf(-gv0)) * uv0;
                    const float h1 = gv1 / (1.0f + expf(-gv1)) * uv1;
                    const int col = jn8 * 8 + ((lane & 3) << 1);
                    *(uint32_t*)(hrow + col) = cvt2(h0, h1);
                }
            }
        }
    } else {
        const int n0 = blockIdx.y * BN;
        #pragma unroll
        for (int im = 0; im < 2; im++) {
            #pragma unroll
            for (int half = 0; half < 2; half++) {
                const int rloc = wm + im * 16 + half * 8 + (lane >> 2);
                if (rloc >= mrows) continue;
                const int   tok  = g_perm_token[m0 + rloc];
                const float gate = g_perm_gate[m0 + rloc];
                #pragma unroll
                for (int jn8 = 0; jn8 < 8; jn8++) {
                    const int col = n0 + wn + jn8 * 8 + ((lane & 3) << 1);
                    float* dst = outp + (size_t)tok * HDIM + col;
                    atomicAdd(dst + 0, gate * acc[im][jn8][half * 2 + 0]);
                    atomicAdd(dst + 1, gate * acc[im][jn8][half * 2 + 1]);
                }
            }
        }
    }
}

// ================= launch =================
extern "C" void kernel_launch(void* const* d_in, const int* in_sizes, int n_in,
                              void* d_out, int out_size)
{
    const float* hs     = (const float*)d_in[0];
    const float* logits = (const float*)d_in[1];
    const float* w13    = (const float*)d_in[2];
    const float* w2     = (const float*)d_in[3];
    float* out = (float*)d_out;

    cudaFuncSetAttribute(gemm_fused<HDIM, 1, 1>, cudaFuncAttributeMaxDynamicSharedMemorySize, SMEM_BYTES);
    cudaFuncSetAttribute(gemm_fused<IDIM, 2, 2>, cudaFuncAttributeMaxDynamicSharedMemorySize, SMEM_BYTES);

    zero_kernel<<<(T_TOK * HDIM / 4 + 255) / 256, 256>>>((float4*)out);
    route_kernel<<<1, 256>>>(logits);
    permA_kernel<<<(NASSIGN * HDIM / 4 + 255) / 256, 256>>>(hs);

    // GEMM1: grid (M-tiles, IDIM/64 h-col blocks)
    gemm_fused<HDIM, 1, 1><<<dim3(MAXT, IDIM / 64, 1), 256, SMEM_BYTES>>>(w13, nullptr);
    // GEMM2: grid (M-tiles, HDIM/128, split-K 2)
    gemm_fused<IDIM, 2, 2><<<dim3(MAXT, HDIM / BN, 2), 256, SMEM_BYTES>>>(w2, out);
}

// round 16
// speedup vs baseline: 1.2245x; 1.1371x over previous
#include <cuda_runtime.h>
#include <cuda_fp16.h>
#include <math.h>
#include <stdint.h>

#define T_TOK   2048
#define HDIM    2048
#define NEXP    8
#define IDIM    5632
#define TWOI    11264
#define NASSIGN 4096
#define MAXT    40
#define PADROWS (NASSIGN + 256)

#define BM 128
#define BN 128
#define BK 32
#define PITCH 40                 // fp16 elems per tile row (80B)

// smem layout (bytes): A fp16 x3, B fp16 tile x2
#define ATSZ 10240
#define AT_OFF(k) ((k) * ATSZ)             // 0, 10240, 20480
#define BT_OFF(k) (30720 + (k) * ATSZ)     // 30720, 40960
#define SMEM_BYTES 51200

// ---------------- routing / scheduling state ----------------
__device__ int   g_perm_token[NASSIGN];
__device__ float g_perm_gate[NASSIGN];
__device__ int   g_se[MAXT], g_sm0[MAXT], g_srows[MAXT];

// ---------------- fp16 operands / scratch ----------------
__device__ __align__(128) __half g_af[(size_t)PADROWS * HDIM];   // gathered X fp16
__device__ __align__(128) __half g_h [(size_t)PADROWS * IDIM];   // activation fp16

// ================= helpers =================
__device__ __forceinline__ uint32_t smem_to_u32(const void* p) {
    uint32_t a;
    asm("{ .reg .u64 t; cvta.to.shared.u64 t, %1; cvt.u32.u64 %0, t; }" : "=r"(a) : "l"(p));
    return a;
}
__device__ __forceinline__ void cp16(uint32_t dst, const void* src) {
    asm volatile("cp.async.cg.shared.global [%0], [%1], 16;" :: "r"(dst), "l"(src));
}
__device__ __forceinline__ void ldsm4(uint32_t* r, uint32_t addr) {
    asm volatile("ldmatrix.sync.aligned.m8n8.x4.shared.b16 {%0,%1,%2,%3}, [%4];"
                 : "=r"(r[0]), "=r"(r[1]), "=r"(r[2]), "=r"(r[3]) : "r"(addr));
}
__device__ __forceinline__ void mma16816(float* d, const uint32_t* a, const uint32_t* b) {
    asm volatile(
        "mma.sync.aligned.m16n8k16.row.col.f32.f16.f16.f32 "
        "{%0,%1,%2,%3}, {%4,%5,%6,%7}, {%8,%9}, {%0,%1,%2,%3};"
        : "+f"(d[0]), "+f"(d[1]), "+f"(d[2]), "+f"(d[3])
        : "r"(a[0]), "r"(a[1]), "r"(a[2]), "r"(a[3]), "r"(b[0]), "r"(b[1]));
}
__device__ __forceinline__ void sts64(uint32_t a, uint32_t x, uint32_t y) {
    asm volatile("st.shared.v2.b32 [%0], {%1,%2};" :: "r"(a), "r"(x), "r"(y));
}
__device__ __forceinline__ uint32_t cvt2(float f0, float f1) {
    __half2 hh = __floats2half2_rn(f0, f1);
    return *(uint32_t*)&hh;
}

// ================= routing =================
__global__ void route_kernel(const float* __restrict__ logits)
{
    __shared__ int s_cnt[NEXP], s_off[NEXP + 1], s_cur[NEXP];
    const int tid = threadIdx.x;
    if (tid < NEXP) s_cnt[tid] = 0;
    __syncthreads();
    for (int t = tid; t < T_TOK; t += blockDim.x) {
        const float* l = logits + t * NEXP;
        int i1 = 0; float v1 = l[0];
        #pragma unroll
        for (int e = 1; e < NEXP; e++) { float v = l[e]; if (v > v1) { v1 = v; i1 = e; } }
        int i2 = -1; float v2 = -3.0e38f;
        #pragma unroll
        for (int e = 0; e < NEXP; e++) { if (e == i1) continue; float v = l[e]; if (v > v2) { v2 = v; i2 = e; } }
        atomicAdd(&s_cnt[i1], 1); atomicAdd(&s_cnt[i2], 1);
    }
    __syncthreads();
    if (tid == 0) {
        int acc = 0;
        for (int e = 0; e < NEXP; e++) { s_off[e] = acc; s_cur[e] = acc; acc += s_cnt[e]; }
        s_off[NEXP] = acc;
    }
    __syncthreads();
    for (int t = tid; t < T_TOK; t += blockDim.x) {
        const float* l = logits + t * NEXP;
        int i1 = 0; float v1 = l[0];
        #pragma unroll
        for (int e = 1; e < NEXP; e++) { float v = l[e]; if (v > v1) { v1 = v; i1 = e; } }
        int i2 = -1; float v2 = -3.0e38f;
        #pragma unroll
        for (int e = 0; e < NEXP; e++) { if (e == i1) continue; float v = l[e]; if (v > v2) { v2 = v; i2 = e; } }
        float g1 = 1.0f / (1.0f + expf(v2 - v1));
        float g2 = 1.0f - g1;
        int s1 = atomicAdd(&s_cur[i1], 1);
        g_perm_token[s1] = t; g_perm_gate[s1] = g1;
        int s2 = atomicAdd(&s_cur[i2], 1);
        g_perm_token[s2] = t; g_perm_gate[s2] = g2;
    }
    __syncthreads();
    if (tid == 0) {
        int nt = 0;
        for (int e = 0; e < NEXP; e++) {
            int off = s_off[e], cnt = s_cnt[e];
            for (int r = 0; r < cnt; r += BM) {
                g_se[nt] = e; g_sm0[nt] = off + r;
                g_srows[nt] = (cnt - r < BM) ? (cnt - r) : BM; nt++;
            }
        }
        for (; nt < MAXT; nt++) g_srows[nt] = 0;
    }
}

__global__ void zero_kernel(float4* __restrict__ out)
{
    int idx = blockIdx.x * blockDim.x + threadIdx.x;
    if (idx < (T_TOK * HDIM) / 4) out[idx] = make_float4(0.f, 0.f, 0.f, 0.f);
}

// gather X rows by perm token -> fp16
__global__ void permA_kernel(const float* __restrict__ X)
{
    int idx = blockIdx.x * blockDim.x + threadIdx.x;
    if (idx >= NASSIGN * HDIM / 4) return;
    int r = idx / (HDIM / 4);
    int c = (idx % (HDIM / 4)) * 4;
    int t = g_perm_token[r];
    float4 x = *(const float4*)(X + (size_t)t * HDIM + c);
    uint2 p; p.x = cvt2(x.x, x.y); p.y = cvt2(x.z, x.w);
    *(uint2*)(g_af + (size_t)r * HDIM + c) = p;
}

// ============ 128x128 GEMM, 256 thr, 2 CTA/SM; B fp32 via LDG->reg->cvt->STS ============
// EPI 1: A = g_af, B = w13 fp32 (g/u paired rows), fused silu -> g_h
// EPI 2: A = g_h,  B = w2 fp32, gated atomicAdd -> out
template<int KD, int EPI, int KSPLIT>
__global__ __launch_bounds__(256, 2) void gemm_fused(
    const float* __restrict__ W, float* __restrict__ outp)
{
    constexpr int NCH = KD / (BK * KSPLIT);

    const int bt    = blockIdx.x;
    const int mrows = g_srows[bt];
    if (mrows == 0) return;
    const int e   = g_se[bt];
    const int m0  = g_sm0[bt];
    const int kk0 = (KSPLIT > 1) ? blockIdx.z * (KD / KSPLIT) : 0;
    const float* Bw = W + (size_t)e * ((EPI == 1) ? (size_t)TWOI * KD : (size_t)HDIM * KD);

    extern __shared__ char smem[];
    const uint32_t sb = smem_to_u32(smem);
    const int tid  = threadIdx.x;
    const int wid  = tid >> 5;
    const int lane = tid & 31;
    const int wm   = (wid & 3) << 5;    // 0..96
    const int wn   = (wid >> 2) << 6;   // 0 or 64

    // ---- A fp16 cp.async endpoints: 2 chunks/thread ----
    const __half* Aarr = (EPI == 1) ? g_af : g_h;
    const __half* srcA0 = Aarr + (size_t)(m0 + (tid >> 2)) * KD + kk0 + (tid & 3) * 8;
    const __half* srcA1 = srcA0 + (size_t)64 * KD;
    const uint32_t dA0 = ((tid >> 2) * PITCH + (tid & 3) * 8) * 2;
    const uint32_t dA1 = dA0 + 64 * PITCH * 2;

    // ---- B fp32 LDG endpoints: 4 float4/thread (rows tid>>3 + {0,32,64,96}) ----
    const float* srcB[4];
    {
        const int rb = tid >> 3, cg = (tid & 7) * 4;
        #pragma unroll
        for (int j = 0; j < 4; j++) {
            const int r = rb + j * 32;
            int grow;
            if (EPI == 1) {
                const int wg = r >> 6, inner = r & 63;
                const int n0g = blockIdx.y * 64;
                grow = (inner < 32) ? (n0g + wg * 32 + inner)
                                    : (IDIM + n0g + wg * 32 + inner - 32);
            } else {
                grow = blockIdx.y * BN + r;
            }
            srcB[j] = Bw + (size_t)grow * KD + kk0 + cg;
        }
    }
    // STS destination for this thread's 4 rows (fp16 tile offsets)
    const uint32_t dBt = ((tid >> 3) * PITCH + (tid & 7) * 4) * 2;   // +j*32*PITCH*2

    const uint32_t a_off = ((wm + (lane & 15)) * PITCH + ((lane >> 4) << 3)) * 2;
    const uint32_t b_off = ((wn + ((lane >> 4) << 3) + (lane & 7)) * PITCH + (((lane >> 3) & 1) << 3)) * 2;

    float acc[2][8][4];
    #pragma unroll
    for (int i = 0; i < 2; i++)
        #pragma unroll
        for (int j = 0; j < 8; j++)
            #pragma unroll
            for (int q = 0; q < 4; q++) acc[i][j][q] = 0.f;

    float4 r4[4];   // B fp32 in flight (stage i+1's values during iter i)

    // ---- prologue ----
    cp16(sb + AT_OFF(0) + dA0, srcA0); cp16(sb + AT_OFF(0) + dA1, srcA1);
    asm volatile("cp.async.commit_group;" ::: "memory");
    srcA0 += BK; srcA1 += BK;
    if (NCH > 1) {
        cp16(sb + AT_OFF(1) + dA0, srcA0); cp16(sb + AT_OFF(1) + dA1, srcA1);
        srcA0 += BK; srcA1 += BK;
    }
    asm volatile("cp.async.commit_group;" ::: "memory");

    // B stage 0 -> regs -> BT0
    #pragma unroll
    for (int j = 0; j < 4; j++) r4[j] = *(const float4*)(srcB[j]);
    #pragma unroll
    for (int j = 0; j < 4; j++) {
        sts64(sb + BT_OFF(0) + dBt + j * 32 * PITCH * 2,
              cvt2(r4[j].x, r4[j].y), cvt2(r4[j].z, r4[j].w));
    }
    // B stage 1 -> regs
    if (NCH > 1) {
        #pragma unroll
        for (int j = 0; j < 4; j++) r4[j] = *(const float4*)(srcB[j] + BK);
    }
    #pragma unroll
    for (int j = 0; j < 4; j++) srcB[j] += 2 * BK;

    for (int i = 0; i < NCH; i++) {
        __syncthreads();   // BT(i) visible; all warps done with mma(i-1) (frees AT[(i+2)%3], BT[(i+1)%2])

        // issue A(i+2)
        if (i + 2 < NCH) {
            const uint32_t at = sb + AT_OFF((i + 2) % 3);
            cp16(at + dA0, srcA0); cp16(at + dA1, srcA1);
            srcA0 += BK; srcA1 += BK;
        }
        asm volatile("cp.async.commit_group;" ::: "memory");

        // STS B(i+1) from regs (loaded last iter), then LDG B(i+2)
        if (i + 1 < NCH) {
            const uint32_t bt1 = sb + BT_OFF((i + 1) & 1);
            #pragma unroll
            for (int j = 0; j < 4; j++)
                sts64(bt1 + dBt + j * 32 * PITCH * 2,
                      cvt2(r4[j].x, r4[j].y), cvt2(r4[j].z, r4[j].w));
        }
        if (i + 2 < NCH) {
            #pragma unroll
            for (int j = 0; j < 4; j++) { r4[j] = *(const float4*)(srcB[j]); srcB[j] += BK; }
        }

        // ensure AT(i) arrived (groups i+1, i+2 may still be in flight)
        asm volatile("cp.async.wait_group 2;" ::: "memory");

        // mma on stage i
        const uint32_t at  = sb + AT_OFF(i % 3);
        const uint32_t btt = sb + BT_OFF(i & 1);
        #pragma unroll
        for (int ks = 0; ks < BK; ks += 16) {
            uint32_t afr[2][4], bfr[4][4];
            ldsm4(afr[0], at + a_off + ks * 2);
            ldsm4(afr[1], at + a_off + (16 * PITCH + ks) * 2);
            #pragma unroll
            for (int jn = 0; jn < 4; jn++)
                ldsm4(bfr[jn], btt + b_off + (jn * 16 * PITCH + ks) * 2);
            #pragma unroll
            for (int im = 0; im < 2; im++)
                #pragma unroll
                for (int jn = 0; jn < 4; jn++) {
                    mma16816(acc[im][2 * jn],     afr[im], &bfr[jn][0]);
                    mma16816(acc[im][2 * jn + 1], afr[im], &bfr[jn][2]);
                }
        }
    }

    // ---------------- epilogue ----------------
    if (EPI == 1) {
        const int n0g  = blockIdx.y * 64;
        const int wg32 = (wn >> 6) * 32;
        #pragma unroll
        for (int im = 0; im < 2; im++) {
            #pragma unroll
            for (int half = 0; half < 2; half++) {
                const int rloc = wm + im * 16 + half * 8 + (lane >> 2);
                if (rloc >= mrows) continue;
                __half* hrow = g_h + (size_t)(m0 + rloc) * IDIM + n0g + wg32;
                #pragma unroll
                for (int jn8 = 0; jn8 < 4; jn8++) {
                    const float gv0 = acc[im][jn8][half * 2 + 0];
                    const float gv1 = acc[im][jn8][half * 2 + 1];
                    const float uv0 = acc[im][jn8 + 4][half * 2 + 0];
                    const float uv1 = acc[im][jn8 + 4][half * 2 + 1];
                    const float h0 = gv0 / (1.0f + expf(-gv0)) * uv0;
                    const float h1 = gv1 / (1.0f + expf(-gv1)) * uv1;
                    const int col = jn8 * 8 + ((lane & 3) << 1);
                    *(uint32_t*)(hrow + col) = cvt2(h0, h1);
                }
            }
        }
    } else {
        const int n0 = blockIdx.y * BN;
        #pragma unroll
        for (int im = 0; im < 2; im++) {
            #pragma unroll
            for (int half = 0; half < 2; half++) {
                const int rloc = wm + im * 16 + half * 8 + (lane >> 2);
                if (rloc >= mrows) continue;
                const int   tok  = g_perm_token[m0 + rloc];
                const float gate = g_perm_gate[m0 + rloc];
                #pragma unroll
                for (int jn8 = 0; jn8 < 8; jn8++) {
                    const int col = n0 + wn + jn8 * 8 + ((lane & 3) << 1);
                    float* dst = outp + (size_t)tok * HDIM + col;
                    atomicAdd(dst + 0, gate * acc[im][jn8][half * 2 + 0]);
                    atomicAdd(dst + 1, gate * acc[im][jn8][half * 2 + 1]);
                }
            }
        }
    }
}

// ================= launch =================
extern "C" void kernel_launch(void* const* d_in, const int* in_sizes, int n_in,
                              void* d_out, int out_size)
{
    const float* hs     = (const float*)d_in[0];
    const float* logits = (const float*)d_in[1];
    const float* w13    = (const float*)d_in[2];
    const float* w2     = (const float*)d_in[3];
    float* out = (float*)d_out;

    cudaFuncSetAttribute(gemm_fused<HDIM, 1, 1>, cudaFuncAttributeMaxDynamicSharedMemorySize, SMEM_BYTES);
    cudaFuncSetAttribute(gemm_fused<IDIM, 2, 4>, cudaFuncAttributeMaxDynamicSharedMemorySize, SMEM_BYTES);

    zero_kernel<<<(T_TOK * HDIM / 4 + 255) / 256, 256>>>((float4*)out);
    route_kernel<<<1, 256>>>(logits);
    permA_kernel<<<(NASSIGN * HDIM / 4 + 255) / 256, 256>>>(hs);

    // GEMM1: grid (M-tiles, IDIM/64 h-col blocks)
    gemm_fused<HDIM, 1, 1><<<dim3(MAXT, IDIM / 64, 1), 256, SMEM_BYTES>>>(w13, nullptr);
    // GEMM2: grid (M-tiles, HDIM/128, split-K 4)
    gemm_fused<IDIM, 2, 4><<<dim3(MAXT, HDIM / BN, 4), 256, SMEM_BYTES>>>(w2, out);
}